// round 1
// baseline (speedup 1.0000x reference)
#include <cuda_runtime.h>
#include <stdint.h>

// Problem constants (fixed-shape problem)
#define N_ITEMS 8192
#define D_IN    1024
#define E_OUT   1024
#define K_TYPES 8
#define OUT_COLS (E_OUT + K_TYPES)   // 1032

// GEMM tile config
#define BM 128
#define BN 64
#define BK 16
#define MAX_TILES (N_ITEMS / BM + K_TYPES)   // 72

// ---------------- device scratch (no allocations allowed) ----------------
__device__ int g_counts[K_TYPES];
__device__ int g_cursors[K_TYPES];
__device__ int g_perm[N_ITEMS];
__device__ int g_tile_type[MAX_TILES];
__device__ int g_tile_base[MAX_TILES];
__device__ int g_tile_rows[MAX_TILES];
__device__ int g_num_tiles;
__device__ int g_is64;   // 1 if type_ids buffer is int64, 0 if int32

// ---------------- dtype detection for type_ids ----------------
// If the buffer is little-endian int64 with values in [0,8), every odd
// int32 word is 0. If it is int32 (values uniform in [0,8)), the chance
// that 32 odd words are all zero is 8^-32 ~ 0. Deterministic per-input.
__global__ void detect_kernel(const int* tid32) {
    unsigned int lane = threadIdx.x;
    int v = tid32[2 * lane + 1];
    unsigned int ballot = __ballot_sync(0xFFFFFFFFu, v == 0);
    if (lane == 0) g_is64 = (ballot == 0xFFFFFFFFu) ? 1 : 0;
    if (lane < K_TYPES) g_counts[lane] = 0;
}

__device__ __forceinline__ int load_type(const int* tid32, int n) {
    // low 32-bit word holds the value in both layouts
    return g_is64 ? tid32[2 * n] : tid32[n];
}

// ---------------- routing: count -> scan -> scatter ----------------
__global__ void count_kernel(const int* tid32) {
    int n = blockIdx.x * blockDim.x + threadIdx.x;
    if (n < N_ITEMS) atomicAdd(&g_counts[load_type(tid32, n)], 1);
}

__global__ void scan_kernel() {
    // single thread: K=8, trivial
    int off = 0, nt = 0;
    for (int k = 0; k < K_TYPES; k++) {
        g_cursors[k] = off;
        int c = g_counts[k];
        for (int t = 0; t < c; t += BM) {
            g_tile_type[nt] = k;
            g_tile_base[nt] = off + t;
            g_tile_rows[nt] = min(BM, c - t);
            nt++;
        }
        off += c;
    }
    g_num_tiles = nt;
}

__global__ void scatter_kernel(const int* tid32) {
    int n = blockIdx.x * blockDim.x + threadIdx.x;
    if (n < N_ITEMS) {
        int k = load_type(tid32, n);
        int pos = atomicAdd(&g_cursors[k], 1);
        g_perm[pos] = n;
    }
}

// ---------------- grouped gathered SGEMM ----------------
// grid: (MAX_TILES, E_OUT/BN). Each CTA: one 128-row tile of one type x one
// 64-col tile. A rows gathered via g_perm; B = W[k] tile (contiguous).
__global__ __launch_bounds__(256, 3) void gemm_kernel(
    const float* __restrict__ x, const float* __restrict__ W,
    const float* __restrict__ bias, float* __restrict__ out)
{
    int tile = blockIdx.x;
    if (tile >= g_num_tiles) return;

    const int ktype = g_tile_type[tile];
    const int base  = g_tile_base[tile];
    const int rows  = g_tile_rows[tile];
    const int col0  = blockIdx.y * BN;

    __shared__ float As[BK][BM];      // A transposed: As[k][m]
    __shared__ float Bs[BK][BN];
    __shared__ int   ridx[BM];

    const int tid = threadIdx.x;

    if (tid < BM) ridx[tid] = (tid < rows) ? g_perm[base + tid] : -1;
    __syncthreads();

    const float* Wk = W + (size_t)ktype * D_IN * E_OUT;

    // compute-thread mapping: 16x16 thread grid, each does 8 rows x 4 cols
    const int tx = tid & 15;          // col group
    const int ty = tid >> 4;          // row group
    float acc[8][4];
    #pragma unroll
    for (int i = 0; i < 8; i++)
        #pragma unroll
        for (int j = 0; j < 4; j++) acc[i][j] = 0.0f;

    // A-load mapping: am = row, 2 float4 per thread over the 16 K-columns
    const int am = tid & (BM - 1);
    const int ah = tid >> 7;                 // 0 or 1
    const int myrow = ridx[am];
    const float* xrow = (myrow >= 0) ? (x + (size_t)myrow * D_IN) : x;
    const bool avalid = (myrow >= 0);

    // B-load mapping: one float4 per thread
    const int br = tid >> 4;                 // 0..15 (K row)
    const int bc = (tid & 15) * 4;           // 0..60

    for (int kk = 0; kk < D_IN; kk += BK) {
        // load A tile (gathered rows), store transposed
        #pragma unroll
        for (int h = 0; h < 2; h++) {
            int c = ah * 4 + h * 8;
            float4 v = make_float4(0.f, 0.f, 0.f, 0.f);
            if (avalid) v = *(const float4*)(xrow + kk + c);
            As[c + 0][am] = v.x;
            As[c + 1][am] = v.y;
            As[c + 2][am] = v.z;
            As[c + 3][am] = v.w;
        }
        // load B tile
        {
            float4 v = *(const float4*)(Wk + (size_t)(kk + br) * E_OUT + col0 + bc);
            *(float4*)&Bs[br][bc] = v;
        }
        __syncthreads();

        #pragma unroll
        for (int p = 0; p < BK; p++) {
            float4 a0 = *(const float4*)&As[p][ty * 8];
            float4 a1 = *(const float4*)&As[p][ty * 8 + 4];
            float4 bb = *(const float4*)&Bs[p][tx * 4];
            float av[8] = {a0.x, a0.y, a0.z, a0.w, a1.x, a1.y, a1.z, a1.w};
            float bv[4] = {bb.x, bb.y, bb.z, bb.w};
            #pragma unroll
            for (int i = 0; i < 8; i++)
                #pragma unroll
                for (int j = 0; j < 4; j++)
                    acc[i][j] = fmaf(av[i], bv[j], acc[i][j]);
        }
        __syncthreads();
    }

    // epilogue: add bias, scatter rows to out
    const float* bk = bias + (size_t)ktype * E_OUT + col0 + tx * 4;
    float4 bv4 = *(const float4*)bk;
    #pragma unroll
    for (int i = 0; i < 8; i++) {
        int m = ty * 8 + i;
        int row = ridx[m];
        if (row < 0) continue;
        float4 r;
        r.x = acc[i][0] + bv4.x;
        r.y = acc[i][1] + bv4.y;
        r.z = acc[i][2] + bv4.z;
        r.w = acc[i][3] + bv4.w;
        *(float4*)(out + (size_t)row * OUT_COLS + col0 + tx * 4) = r;
    }
}

// ---------------- one-hot tail ----------------
__global__ void tail_kernel(const int* tid32, float* out) {
    int n = blockIdx.x * blockDim.x + threadIdx.x;
    if (n >= N_ITEMS) return;
    int k = load_type(tid32, n);
    float* p = out + (size_t)n * OUT_COLS + E_OUT;
    float4 lo = make_float4(0.f, 0.f, 0.f, 0.f);
    float4 hi = make_float4(0.f, 0.f, 0.f, 0.f);
    ((float*)&lo)[k & 3] = (k < 4) ? 1.0f : ((float*)&lo)[k & 3];
    if (k < 4) ((float*)&lo)[k] = 1.0f; else ((float*)&hi)[k - 4] = 1.0f;
    *(float4*)(p)     = lo;
    *(float4*)(p + 4) = hi;
}

// ---------------- launch ----------------
extern "C" void kernel_launch(void* const* d_in, const int* in_sizes, int n_in,
                              void* d_out, int out_size) {
    const float* x     = (const float*)d_in[0];
    const int*   tid32 = (const int*)d_in[1];   // int64 or int32, detected
    const float* W     = (const float*)d_in[2];
    const float* b     = (const float*)d_in[3];
    float* out = (float*)d_out;

    detect_kernel<<<1, 32>>>(tid32);
    count_kernel<<<N_ITEMS / 256, 256>>>(tid32);
    scan_kernel<<<1, 1>>>();
    scatter_kernel<<<N_ITEMS / 256, 256>>>(tid32);

    dim3 grid(MAX_TILES, E_OUT / BN);
    gemm_kernel<<<grid, 256>>>(x, W, b, out);

    tail_kernel<<<N_ITEMS / 256, 256>>>(tid32, out);
}

// round 3
// speedup vs baseline: 2.8155x; 2.8155x over previous
#include <cuda_runtime.h>
#include <cuda_fp16.h>
#include <stdint.h>

// ---------------- problem constants ----------------
#define N_ITEMS 8192
#define D_IN    1024
#define E_OUT   1024
#define K_TYPES 8
#define OUT_COLS (E_OUT + K_TYPES)   // 1032

// ---------------- GEMM tiling ----------------
#define BM 128
#define BN 128
#define BK 32
#define KPRIME 2048                   // 2 split segments * 1024
#define NITER (KPRIME / BK)           // 64
#define MAX_TILES (N_ITEMS / BM + K_TYPES)   // 72

// smem strides (bytes), padded for conflict-free ldmatrix
#define A_STRIDE 80                   // 64B row + 16B pad
#define B_STRIDE 272                  // 256B row + 16B pad
#define SZA (BM * A_STRIDE)           // 10240
#define SZB (BK * B_STRIDE)           // 8704

// ---------------- device scratch ----------------
__device__ int g_counts[K_TYPES];
__device__ int g_cursors[K_TYPES];
__device__ int g_perm[N_ITEMS];
__device__ int g_tile_type[MAX_TILES];
__device__ int g_tile_base[MAX_TILES];
__device__ int g_tile_rows[MAX_TILES];
__device__ int g_num_tiles;
__device__ int g_is64;

__device__ __half g_xh[(size_t)N_ITEMS * D_IN];   // 16 MB
__device__ __half g_xl[(size_t)N_ITEMS * D_IN];   // 16 MB
__device__ __half g_wh[(size_t)K_TYPES * D_IN * E_OUT];  // 16 MB, layout [k][d][e]

// ---------------- PTX helpers ----------------
__device__ __forceinline__ uint32_t smem_u32(const void* p) {
    uint32_t a;
    asm("{ .reg .u64 t; cvta.to.shared.u64 t, %1; cvt.u32.u64 %0, t; }" : "=r"(a) : "l"(p));
    return a;
}

#define CP_ASYNC16(dst, src, sz) \
    asm volatile("cp.async.cg.shared.global [%0], [%1], 16, %2;" \
                 :: "r"(dst), "l"(src), "r"(sz) : "memory")
#define CP_COMMIT() asm volatile("cp.async.commit_group;" ::: "memory")
#define CP_WAIT(n)  asm volatile("cp.async.wait_group %0;" :: "n"(n) : "memory")

__device__ __forceinline__ void ldmatrix_x4(uint32_t& r0, uint32_t& r1, uint32_t& r2,
                                            uint32_t& r3, uint32_t addr) {
    asm volatile("ldmatrix.sync.aligned.m8n8.x4.shared.b16 {%0,%1,%2,%3}, [%4];"
                 : "=r"(r0), "=r"(r1), "=r"(r2), "=r"(r3) : "r"(addr));
}
__device__ __forceinline__ void ldmatrix_x4_trans(uint32_t& r0, uint32_t& r1, uint32_t& r2,
                                                  uint32_t& r3, uint32_t addr) {
    asm volatile("ldmatrix.sync.aligned.m8n8.x4.trans.shared.b16 {%0,%1,%2,%3}, [%4];"
                 : "=r"(r0), "=r"(r1), "=r"(r2), "=r"(r3) : "r"(addr));
}
__device__ __forceinline__ void mma16816(float* c, const uint32_t* a, const uint32_t* b) {
    asm volatile(
        "mma.sync.aligned.m16n8k16.row.col.f32.f16.f16.f32 "
        "{%0,%1,%2,%3}, {%4,%5,%6,%7}, {%8,%9}, {%0,%1,%2,%3};"
        : "+f"(c[0]), "+f"(c[1]), "+f"(c[2]), "+f"(c[3])
        : "r"(a[0]), "r"(a[1]), "r"(a[2]), "r"(a[3]), "r"(b[0]), "r"(b[1]));
}

// ---------------- dtype detection for type_ids ----------------
__global__ void detect_kernel(const int* tid32) {
    unsigned int lane = threadIdx.x;
    int v = tid32[2 * lane + 1];
    unsigned int ballot = __ballot_sync(0xFFFFFFFFu, v == 0);
    if (lane == 0) g_is64 = (ballot == 0xFFFFFFFFu) ? 1 : 0;
    if (lane < K_TYPES) g_counts[lane] = 0;
}
__device__ __forceinline__ int load_type(const int* tid32, int n) {
    return g_is64 ? tid32[2 * n] : tid32[n];
}

// ---------------- routing ----------------
__global__ void count_kernel(const int* tid32) {
    int n = blockIdx.x * blockDim.x + threadIdx.x;
    if (n < N_ITEMS) atomicAdd(&g_counts[load_type(tid32, n)], 1);
}
__global__ void scan_kernel() {
    int off = 0, nt = 0;
    for (int k = 0; k < K_TYPES; k++) {
        g_cursors[k] = off;
        int c = g_counts[k];
        for (int t = 0; t < c; t += BM) {
            g_tile_type[nt] = k;
            g_tile_base[nt] = off + t;
            g_tile_rows[nt] = min(BM, c - t);
            nt++;
        }
        off += c;
    }
    g_num_tiles = nt;
}
__global__ void scatter_kernel(const int* tid32) {
    int n = blockIdx.x * blockDim.x + threadIdx.x;
    if (n < N_ITEMS) {
        int k = load_type(tid32, n);
        int pos = atomicAdd(&g_cursors[k], 1);
        g_perm[pos] = n;
    }
}

// ---------------- conversions ----------------
__global__ void convert_x_kernel(const float* __restrict__ x) {
    size_t i = ((size_t)blockIdx.x * blockDim.x + threadIdx.x) * 8;
    float4 v0 = *(const float4*)(x + i);
    float4 v1 = *(const float4*)(x + i + 4);
    float v[8] = {v0.x, v0.y, v0.z, v0.w, v1.x, v1.y, v1.z, v1.w};
    __half h[8], l[8];
#pragma unroll
    for (int j = 0; j < 8; j++) {
        h[j] = __float2half_rn(v[j]);
        l[j] = __float2half_rn(v[j] - __half2float(h[j]));
    }
    *(uint4*)(g_xh + i) = *(uint4*)h;
    *(uint4*)(g_xl + i) = *(uint4*)l;
}
__global__ void convert_w_kernel(const float* __restrict__ W) {
    size_t i = ((size_t)blockIdx.x * blockDim.x + threadIdx.x) * 8;
    float4 v0 = *(const float4*)(W + i);
    float4 v1 = *(const float4*)(W + i + 4);
    float v[8] = {v0.x, v0.y, v0.z, v0.w, v1.x, v1.y, v1.z, v1.w};
    __half h[8];
#pragma unroll
    for (int j = 0; j < 8; j++) h[j] = __float2half_rn(v[j]);
    *(uint4*)(g_wh + i) = *(uint4*)h;
}

// ---------------- grouped fp16 mma.sync GEMM ----------------
// grid: (MAX_TILES, E_OUT/BN). CTA = 128 gathered rows x 128 cols.
// K' = 2048: segment 0 = xh @ Wh, segment 1 = xl @ Wh (accumulated).
__global__ void __launch_bounds__(256, 2) gemm_mma_kernel(
    const float* __restrict__ bias, float* __restrict__ out)
{
    const int tile = blockIdx.x;
    if (tile >= g_num_tiles) return;

    __shared__ __align__(16) char smA[2][SZA];
    __shared__ __align__(16) char smB[2][SZB];
    __shared__ int   ridx[BM];
    __shared__ float bs[BN];

    const int tid  = threadIdx.x;
    const int lane = tid & 31;
    const int wid  = tid >> 5;
    const int warp_m = wid & 3;        // 0..3  -> m offset 32*warp_m
    const int warp_n = wid >> 2;       // 0..1  -> n offset 64*warp_n

    const int ktype = g_tile_type[tile];
    const int rbase = g_tile_base[tile];
    const int rows  = g_tile_rows[tile];
    const int col0  = blockIdx.y * BN;

    if (tid < BM) ridx[tid] = (tid < rows) ? g_perm[rbase + tid] : -1;
    if (tid < BN) bs[tid] = bias[(size_t)ktype * E_OUT + col0 + tid];
    __syncthreads();

    // ---- per-thread cp.async descriptors ----
    // A: thread t loads 32B of row ar at fp16-col ac (two 16B chunks)
    const int ar = tid >> 1;
    const int ac = (tid & 1) * 16;
    const int arow = ridx[ar];
    const uint32_t asz = (arow >= 0) ? 16u : 0u;
    const size_t aoff = (size_t)(arow >= 0 ? arow : 0) * D_IN + ac;
    const uint32_t aDst = smem_u32(&smA[0][0]) + (uint32_t)(ar * A_STRIDE + (tid & 1) * 32);
    // B: thread t loads 32B of k-row br at fp16-col bc*8 and bc*8+64
    const int br = tid >> 3;
    const int bc = tid & 7;
    const size_t boff = (size_t)(ktype * D_IN) * E_OUT + (size_t)br * E_OUT + col0 + bc * 8;
    const uint32_t bDst = smem_u32(&smB[0][0]) + (uint32_t)(br * B_STRIDE + bc * 16);

    auto stage_load = [&](int s) {
        const int buf = s & 1;
        const int seg = s >> 5;                 // 0: xh, 1: xl
        const int kk  = (s & 31) * BK;          // k within [0,1024)
        const __half* asrc = ((seg == 0) ? g_xh : g_xl) + aoff + kk;
        const __half* bsrc = g_wh + boff + (size_t)kk * E_OUT;
        CP_ASYNC16(aDst + buf * SZA,      asrc,     asz);
        CP_ASYNC16(aDst + buf * SZA + 16, asrc + 8, asz);
        CP_ASYNC16(bDst + buf * SZB,       bsrc,      16u);
        CP_ASYNC16(bDst + buf * SZB + 128, bsrc + 64, 16u);
    };

    // ---- fragment addresses ----
    // A ldmatrix.x4: lanes 0-15 -> rows m0..15 (k0-7), lanes 16-31 -> +16B (k8-15)
    const uint32_t aBase = smem_u32(&smA[0][0]) +
        (uint32_t)((warp_m * 32 + (lane & 15)) * A_STRIDE + (lane >> 4) * 16);
    // B ldmatrix.x4.trans: lanes 0-15 -> k rows 0..15, lanes 16-31 -> +16B (n+8)
    const uint32_t bBase = smem_u32(&smB[0][0]) +
        (uint32_t)((lane & 15) * B_STRIDE + (lane >> 4) * 16 + warp_n * 128);

    float acc[2][8][4];
#pragma unroll
    for (int mi = 0; mi < 2; mi++)
#pragma unroll
        for (int ni = 0; ni < 8; ni++)
#pragma unroll
            for (int j = 0; j < 4; j++) acc[mi][ni][j] = 0.0f;

    stage_load(0);
    CP_COMMIT();

    for (int s = 0; s < NITER; s++) {
        const int buf = s & 1;
        if (s + 1 < NITER) {
            stage_load(s + 1);
            CP_COMMIT();
            CP_WAIT(1);
        } else {
            CP_WAIT(0);
        }
        __syncthreads();

#pragma unroll
        for (int kst = 0; kst < 2; kst++) {
            uint32_t afr[2][4];
#pragma unroll
            for (int mi = 0; mi < 2; mi++)
                ldmatrix_x4(afr[mi][0], afr[mi][1], afr[mi][2], afr[mi][3],
                            aBase + buf * SZA + mi * 16 * A_STRIDE + kst * 32);
            uint32_t bfr[8][2];
#pragma unroll
            for (int nj = 0; nj < 4; nj++)
                ldmatrix_x4_trans(bfr[2 * nj][0], bfr[2 * nj][1],
                                  bfr[2 * nj + 1][0], bfr[2 * nj + 1][1],
                                  bBase + buf * SZB + kst * 16 * B_STRIDE + nj * 32);
#pragma unroll
            for (int mi = 0; mi < 2; mi++)
#pragma unroll
                for (int ni = 0; ni < 8; ni++)
                    mma16816(acc[mi][ni], afr[mi], bfr[ni]);
        }
        __syncthreads();
    }

    // ---- epilogue: bias + gathered store ----
#pragma unroll
    for (int mi = 0; mi < 2; mi++) {
        const int r0 = warp_m * 32 + mi * 16 + (lane >> 2);
        const int r1 = r0 + 8;
        const int g0 = ridx[r0];
        const int g1 = ridx[r1];
#pragma unroll
        for (int ni = 0; ni < 8; ni++) {
            const int col = warp_n * 64 + ni * 8 + (lane & 3) * 2;
            const float b0 = bs[col], b1 = bs[col + 1];
            if (g0 >= 0) {
                float2 v = {acc[mi][ni][0] + b0, acc[mi][ni][1] + b1};
                *(float2*)(out + (size_t)g0 * OUT_COLS + col0 + col) = v;
            }
            if (g1 >= 0) {
                float2 v = {acc[mi][ni][2] + b0, acc[mi][ni][3] + b1};
                *(float2*)(out + (size_t)g1 * OUT_COLS + col0 + col) = v;
            }
        }
    }
}

// ---------------- one-hot tail ----------------
__global__ void tail_kernel(const int* tid32, float* out) {
    int n = blockIdx.x * blockDim.x + threadIdx.x;
    if (n >= N_ITEMS) return;
    int k = load_type(tid32, n);
    float v[8] = {0.f, 0.f, 0.f, 0.f, 0.f, 0.f, 0.f, 0.f};
    v[k] = 1.0f;
    float* p = out + (size_t)n * OUT_COLS + E_OUT;
    *(float4*)(p)     = make_float4(v[0], v[1], v[2], v[3]);
    *(float4*)(p + 4) = make_float4(v[4], v[5], v[6], v[7]);
}

// ---------------- launch ----------------
extern "C" void kernel_launch(void* const* d_in, const int* in_sizes, int n_in,
                              void* d_out, int out_size) {
    const float* x     = (const float*)d_in[0];
    const int*   tid32 = (const int*)d_in[1];
    const float* W     = (const float*)d_in[2];
    const float* b     = (const float*)d_in[3];
    float* out = (float*)d_out;

    detect_kernel<<<1, 32>>>(tid32);
    count_kernel<<<N_ITEMS / 256, 256>>>(tid32);
    scan_kernel<<<1, 1>>>();
    scatter_kernel<<<N_ITEMS / 256, 256>>>(tid32);

    convert_x_kernel<<<(N_ITEMS * D_IN / 8) / 256, 256>>>(x);
    convert_w_kernel<<<(K_TYPES * D_IN * E_OUT / 8) / 256, 256>>>(W);

    dim3 grid(MAX_TILES, E_OUT / BN);
    gemm_mma_kernel<<<grid, 256>>>(b, out);

    tail_kernel<<<N_ITEMS / 256, 256>>>(tid32, out);
}

// round 5
// speedup vs baseline: 3.3855x; 1.2024x over previous
#include <cuda_runtime.h>
#include <cuda_fp16.h>
#include <stdint.h>

// ---------------- problem constants ----------------
#define N_ITEMS 8192
#define D_IN    1024
#define E_OUT   1024
#define K_TYPES 8
#define OUT_COLS (E_OUT + K_TYPES)   // 1032

// ---------------- GEMM tiling ----------------
#define BM 128
#define BN 128
#define BK 32
#define NITER (D_IN / BK)             // 32 (each iter consumes B once, A twice: xh+xl)
#define NSTAGE 3
#define MAX_TILES (N_ITEMS / BM + K_TYPES)   // 72

// smem strides (bytes), padded for conflict-free ldmatrix
#define A_STRIDE 80                   // 64B row + 16B pad
#define B_STRIDE 272                  // 256B row + 16B pad
#define SZA (BM * A_STRIDE)           // 10240
#define SZB (BK * B_STRIDE)           // 8704
#define DYN_SMEM (NSTAGE * (2 * SZA + SZB))   // 87552

// ---------------- device scratch ----------------
__device__ int g_counts[K_TYPES];
__device__ int g_cursors[K_TYPES];
__device__ int g_perm[N_ITEMS];
__device__ int g_tile_type[MAX_TILES];
__device__ int g_tile_base[MAX_TILES];
__device__ int g_tile_rows[MAX_TILES];
__device__ int g_num_tiles;

__device__ __half g_xh[(size_t)N_ITEMS * D_IN];          // 16 MB
__device__ __half g_xl[(size_t)N_ITEMS * D_IN];          // 16 MB (x residual)
__device__ __half g_wh[(size_t)K_TYPES * D_IN * E_OUT];  // 16 MB, [k][d][e]

// ---------------- PTX helpers ----------------
__device__ __forceinline__ uint32_t smem_u32(const void* p) {
    uint32_t a;
    asm("{ .reg .u64 t; cvta.to.shared.u64 t, %1; cvt.u32.u64 %0, t; }" : "=r"(a) : "l"(p));
    return a;
}

#define CP_ASYNC16(dst, src, sz) \
    asm volatile("cp.async.cg.shared.global [%0], [%1], 16, %2;" \
                 :: "r"(dst), "l"(src), "r"(sz) : "memory")
#define CP_COMMIT() asm volatile("cp.async.commit_group;" ::: "memory")
#define CP_WAIT(n)  asm volatile("cp.async.wait_group %0;" :: "n"(n) : "memory")

__device__ __forceinline__ void ldmatrix_x4(uint32_t& r0, uint32_t& r1, uint32_t& r2,
                                            uint32_t& r3, uint32_t addr) {
    asm volatile("ldmatrix.sync.aligned.m8n8.x4.shared.b16 {%0,%1,%2,%3}, [%4];"
                 : "=r"(r0), "=r"(r1), "=r"(r2), "=r"(r3) : "r"(addr));
}
__device__ __forceinline__ void ldmatrix_x4_trans(uint32_t& r0, uint32_t& r1, uint32_t& r2,
                                                  uint32_t& r3, uint32_t addr) {
    asm volatile("ldmatrix.sync.aligned.m8n8.x4.trans.shared.b16 {%0,%1,%2,%3}, [%4];"
                 : "=r"(r0), "=r"(r1), "=r"(r2), "=r"(r3) : "r"(addr));
}
__device__ __forceinline__ void mma16816(float* c, const uint32_t* a, const uint32_t* b) {
    asm volatile(
        "mma.sync.aligned.m16n8k16.row.col.f32.f16.f16.f32 "
        "{%0,%1,%2,%3}, {%4,%5,%6,%7}, {%8,%9}, {%0,%1,%2,%3};"
        : "+f"(c[0]), "+f"(c[1]), "+f"(c[2]), "+f"(c[3])
        : "r"(a[0]), "r"(a[1]), "r"(a[2]), "r"(a[3]), "r"(b[0]), "r"(b[1]));
}

// ---------------- type_ids dtype detection (per-warp, deterministic) ----------------
__device__ __forceinline__ int detect_is64(const int* tid32) {
    int v = tid32[2 * (threadIdx.x & 31) + 1];
    unsigned int ballot = __ballot_sync(0xFFFFFFFFu, v == 0);
    return ballot == 0xFFFFFFFFu;
}
__device__ __forceinline__ int load_type(const int* tid32, int n, int is64) {
    return is64 ? tid32[2 * n] : tid32[n];
}

// ---------------- routing ----------------
__global__ void zero_kernel() {
    if (threadIdx.x < K_TYPES) g_counts[threadIdx.x] = 0;
}
__global__ void count_kernel(const int* tid32) {
    int is64 = detect_is64(tid32);
    int n = blockIdx.x * blockDim.x + threadIdx.x;
    if (n < N_ITEMS) atomicAdd(&g_counts[load_type(tid32, n, is64)], 1);
}
__global__ void scan_kernel() {
    int off = 0, nt = 0;
    for (int k = 0; k < K_TYPES; k++) {
        g_cursors[k] = off;
        int c = g_counts[k];
        for (int t = 0; t < c; t += BM) {
            g_tile_type[nt] = k;
            g_tile_base[nt] = off + t;
            g_tile_rows[nt] = min(BM, c - t);
            nt++;
        }
        off += c;
    }
    g_num_tiles = nt;
}
__global__ void scatter_kernel(const int* tid32) {
    int is64 = detect_is64(tid32);
    int n = blockIdx.x * blockDim.x + threadIdx.x;
    if (n < N_ITEMS) {
        int k = load_type(tid32, n, is64);
        int pos = atomicAdd(&g_cursors[k], 1);
        g_perm[pos] = n;
    }
}

// ---------------- conversions ----------------
__global__ void convert_x_kernel(const float* __restrict__ x) {
    size_t i = ((size_t)blockIdx.x * blockDim.x + threadIdx.x) * 8;
    float4 v0 = *(const float4*)(x + i);
    float4 v1 = *(const float4*)(x + i + 4);
    float v[8] = {v0.x, v0.y, v0.z, v0.w, v1.x, v1.y, v1.z, v1.w};
    __half h[8], l[8];
#pragma unroll
    for (int j = 0; j < 8; j++) {
        h[j] = __float2half_rn(v[j]);
        l[j] = __float2half_rn(v[j] - __half2float(h[j]));
    }
    *(uint4*)(g_xh + i) = *(uint4*)h;
    *(uint4*)(g_xl + i) = *(uint4*)l;
}
__global__ void convert_w_kernel(const float* __restrict__ W) {
    size_t i = ((size_t)blockIdx.x * blockDim.x + threadIdx.x) * 8;
    float4 v0 = *(const float4*)(W + i);
    float4 v1 = *(const float4*)(W + i + 4);
    float v[8] = {v0.x, v0.y, v0.z, v0.w, v1.x, v1.y, v1.z, v1.w};
    __half h[8];
#pragma unroll
    for (int j = 0; j < 8; j++) h[j] = __float2half_rn(v[j]);
    *(uint4*)(g_wh + i) = *(uint4*)h;
}

// ---------------- grouped fp16 mma.sync GEMM ----------------
// Per k-iter: one B tile (32x128), consumed by BOTH xh and xl A tiles
// (error-compensated product accumulated in fp32). 3-stage cp.async ring.
__global__ void __launch_bounds__(256, 2) gemm_mma_kernel(
    const float* __restrict__ bias, float* __restrict__ out)
{
    const int tile = blockIdx.x;
    if (tile >= g_num_tiles) return;

    extern __shared__ __align__(16) char dynsm[];
    char* smAh = dynsm;                          // NSTAGE x SZA
    char* smAl = dynsm + NSTAGE * SZA;           // NSTAGE x SZA
    char* smB  = dynsm + 2 * NSTAGE * SZA;       // NSTAGE x SZB
    __shared__ int   ridx[BM];
    __shared__ float bs[BN];

    const int tid  = threadIdx.x;
    const int lane = tid & 31;
    const int wid  = tid >> 5;
    const int warp_m = wid & 3;
    const int warp_n = wid >> 2;

    const int ktype = g_tile_type[tile];
    const int rbase = g_tile_base[tile];
    const int rows  = g_tile_rows[tile];
    const int col0  = blockIdx.y * BN;

    if (tid < BM) ridx[tid] = (tid < rows) ? g_perm[rbase + tid] : -1;
    if (tid < BN) bs[tid] = bias[(size_t)ktype * E_OUT + col0 + tid];
    __syncthreads();

    // ---- per-thread cp.async descriptors ----
    const int ar = tid >> 1;
    const int arow = ridx[ar];
    const uint32_t asz = (arow >= 0) ? 16u : 0u;
    const size_t aoff = (size_t)(arow >= 0 ? arow : 0) * D_IN + (tid & 1) * 16;
    const uint32_t ahDst0 = smem_u32(smAh) + (uint32_t)(ar * A_STRIDE + (tid & 1) * 32);
    const uint32_t alDst0 = smem_u32(smAl) + (uint32_t)(ar * A_STRIDE + (tid & 1) * 32);
    const int br = tid >> 3;
    const int bc = tid & 7;
    const size_t boff = (size_t)(ktype * D_IN) * E_OUT + (size_t)br * E_OUT + col0 + bc * 8;
    const uint32_t bDst0 = smem_u32(smB) + (uint32_t)(br * B_STRIDE + bc * 16);

    auto stage_load = [&](int s) {
        const uint32_t buf = (uint32_t)(s % NSTAGE);
        const int kk = s * BK;
        const __half* ah = g_xh + aoff + kk;
        const __half* al = g_xl + aoff + kk;
        const __half* bsrc = g_wh + boff + (size_t)kk * E_OUT;
        const uint32_t ahD = ahDst0 + buf * SZA;
        const uint32_t alD = alDst0 + buf * SZA;
        const uint32_t bD  = bDst0 + buf * SZB;
        CP_ASYNC16(ahD,      ah,     asz);
        CP_ASYNC16(ahD + 16, ah + 8, asz);
        CP_ASYNC16(alD,      al,     asz);
        CP_ASYNC16(alD + 16, al + 8, asz);
        CP_ASYNC16(bD,       bsrc,      16u);
        CP_ASYNC16(bD + 128, bsrc + 64, 16u);
    };

    // ---- fragment base addresses ----
    const uint32_t aFragOff =
        (uint32_t)((warp_m * 32 + (lane & 15)) * A_STRIDE + (lane >> 4) * 16);
    const uint32_t ahBase = smem_u32(smAh) + aFragOff;
    const uint32_t alBase = smem_u32(smAl) + aFragOff;
    const uint32_t bBase = smem_u32(smB) +
        (uint32_t)((lane & 15) * B_STRIDE + (lane >> 4) * 16 + warp_n * 128);

    float acc[2][8][4];
#pragma unroll
    for (int mi = 0; mi < 2; mi++)
#pragma unroll
        for (int ni = 0; ni < 8; ni++)
#pragma unroll
            for (int j = 0; j < 4; j++) acc[mi][ni][j] = 0.0f;

    stage_load(0); CP_COMMIT();
    stage_load(1); CP_COMMIT();

    for (int s = 0; s < NITER; s++) {
        CP_WAIT(1);
        __syncthreads();
        if (s + 2 < NITER) { stage_load(s + 2); CP_COMMIT(); }

        const uint32_t buf = (uint32_t)(s % NSTAGE);
        const uint32_t ahB = ahBase + buf * SZA;
        const uint32_t alB = alBase + buf * SZA;
        const uint32_t bB  = bBase + buf * SZB;
#pragma unroll
        for (int kst = 0; kst < 2; kst++) {
            uint32_t bfr[8][2];
#pragma unroll
            for (int nj = 0; nj < 4; nj++)
                ldmatrix_x4_trans(bfr[2 * nj][0], bfr[2 * nj][1],
                                  bfr[2 * nj + 1][0], bfr[2 * nj + 1][1],
                                  bB + kst * 16 * B_STRIDE + nj * 32);
            uint32_t afr[2][4];
            // xh pass
#pragma unroll
            for (int mi = 0; mi < 2; mi++)
                ldmatrix_x4(afr[mi][0], afr[mi][1], afr[mi][2], afr[mi][3],
                            ahB + mi * 16 * A_STRIDE + kst * 32);
#pragma unroll
            for (int mi = 0; mi < 2; mi++)
#pragma unroll
                for (int ni = 0; ni < 8; ni++)
                    mma16816(acc[mi][ni], afr[mi], bfr[ni]);
            // xl pass (same B fragments)
#pragma unroll
            for (int mi = 0; mi < 2; mi++)
                ldmatrix_x4(afr[mi][0], afr[mi][1], afr[mi][2], afr[mi][3],
                            alB + mi * 16 * A_STRIDE + kst * 32);
#pragma unroll
            for (int mi = 0; mi < 2; mi++)
#pragma unroll
                for (int ni = 0; ni < 8; ni++)
                    mma16816(acc[mi][ni], afr[mi], bfr[ni]);
        }
    }

    // ---- epilogue: bias + gathered store ----
#pragma unroll
    for (int mi = 0; mi < 2; mi++) {
        const int r0 = warp_m * 32 + mi * 16 + (lane >> 2);
        const int r1 = r0 + 8;
        const int g0 = ridx[r0];
        const int g1 = ridx[r1];
#pragma unroll
        for (int ni = 0; ni < 8; ni++) {
            const int col = warp_n * 64 + ni * 8 + (lane & 3) * 2;
            const float b0 = bs[col], b1 = bs[col + 1];
            if (g0 >= 0) {
                float2 v = {acc[mi][ni][0] + b0, acc[mi][ni][1] + b1};
                *(float2*)(out + (size_t)g0 * OUT_COLS + col0 + col) = v;
            }
            if (g1 >= 0) {
                float2 v = {acc[mi][ni][2] + b0, acc[mi][ni][3] + b1};
                *(float2*)(out + (size_t)g1 * OUT_COLS + col0 + col) = v;
            }
        }
    }
}

// ---------------- one-hot tail ----------------
__global__ void tail_kernel(const int* tid32, float* out) {
    int is64 = detect_is64(tid32);
    int n = blockIdx.x * blockDim.x + threadIdx.x;
    if (n >= N_ITEMS) return;
    int k = load_type(tid32, n, is64);
    float v[8] = {0.f, 0.f, 0.f, 0.f, 0.f, 0.f, 0.f, 0.f};
    v[k] = 1.0f;
    float* p = out + (size_t)n * OUT_COLS + E_OUT;
    *(float4*)(p)     = make_float4(v[0], v[1], v[2], v[3]);
    *(float4*)(p + 4) = make_float4(v[4], v[5], v[6], v[7]);
}

// ---------------- launch ----------------
extern "C" void kernel_launch(void* const* d_in, const int* in_sizes, int n_in,
                              void* d_out, int out_size) {
    const float* x     = (const float*)d_in[0];
    const int*   tid32 = (const int*)d_in[1];
    const float* W     = (const float*)d_in[2];
    const float* b     = (const float*)d_in[3];
    float* out = (float*)d_out;

    cudaFuncSetAttribute(gemm_mma_kernel, cudaFuncAttributeMaxDynamicSharedMemorySize,
                         DYN_SMEM);

    zero_kernel<<<1, 32>>>();
    count_kernel<<<N_ITEMS / 256, 256>>>(tid32);
    scan_kernel<<<1, 1>>>();
    scatter_kernel<<<N_ITEMS / 256, 256>>>(tid32);

    convert_x_kernel<<<(N_ITEMS * D_IN / 8) / 256, 256>>>(x);
    convert_w_kernel<<<(K_TYPES * D_IN * E_OUT / 8) / 256, 256>>>(W);

    dim3 grid(MAX_TILES, E_OUT / BN);
    gemm_mma_kernel<<<grid, 256, DYN_SMEM>>>(b, out);

    tail_kernel<<<N_ITEMS / 256, 256>>>(tid32, out);
}

// round 6
// speedup vs baseline: 3.4411x; 1.0164x over previous
#include <cuda_runtime.h>
#include <cuda_fp16.h>
#include <stdint.h>

// ---------------- problem constants ----------------
#define N_ITEMS 8192
#define D_IN    1024
#define E_OUT   1024
#define K_TYPES 8
#define OUT_COLS (E_OUT + K_TYPES)   // 1032

// ---------------- GEMM tiling ----------------
#define BM 128
#define BN 128
#define BK 32
#define NITER (D_IN / BK)             // 32
#define NSTAGE 3
#define MAX_TILES (N_ITEMS / BM + K_TYPES)   // 72

#define A_STRIDE 80
#define B_STRIDE 272
#define SZA (BM * A_STRIDE)           // 10240
#define SZB (BK * B_STRIDE)           // 8704
#define DYN_SMEM (NSTAGE * (2 * SZA + SZB))   // 87552

// ---------------- device scratch ----------------
__device__ int g_perm[N_ITEMS];
__device__ int g_tile_type[MAX_TILES];
__device__ int g_tile_base[MAX_TILES];
__device__ int g_tile_rows[MAX_TILES];
__device__ int g_num_tiles;

__device__ __half g_xh[(size_t)N_ITEMS * D_IN];
__device__ __half g_xl[(size_t)N_ITEMS * D_IN];
__device__ __half g_wh[(size_t)K_TYPES * D_IN * E_OUT];  // [k][d][e]

// ---------------- PTX helpers ----------------
__device__ __forceinline__ uint32_t smem_u32(const void* p) {
    uint32_t a;
    asm("{ .reg .u64 t; cvta.to.shared.u64 t, %1; cvt.u32.u64 %0, t; }" : "=r"(a) : "l"(p));
    return a;
}

#define CP_ASYNC16(dst, src, sz) \
    asm volatile("cp.async.cg.shared.global [%0], [%1], 16, %2;" \
                 :: "r"(dst), "l"(src), "r"(sz) : "memory")
#define CP_COMMIT() asm volatile("cp.async.commit_group;" ::: "memory")
#define CP_WAIT(n)  asm volatile("cp.async.wait_group %0;" :: "n"(n) : "memory")

__device__ __forceinline__ void ldmatrix_x4(uint32_t& r0, uint32_t& r1, uint32_t& r2,
                                            uint32_t& r3, uint32_t addr) {
    asm volatile("ldmatrix.sync.aligned.m8n8.x4.shared.b16 {%0,%1,%2,%3}, [%4];"
                 : "=r"(r0), "=r"(r1), "=r"(r2), "=r"(r3) : "r"(addr));
}
__device__ __forceinline__ void ldmatrix_x4_trans(uint32_t& r0, uint32_t& r1, uint32_t& r2,
                                                  uint32_t& r3, uint32_t addr) {
    asm volatile("ldmatrix.sync.aligned.m8n8.x4.trans.shared.b16 {%0,%1,%2,%3}, [%4];"
                 : "=r"(r0), "=r"(r1), "=r"(r2), "=r"(r3) : "r"(addr));
}
__device__ __forceinline__ void mma16816(float* c, const uint32_t* a, const uint32_t* b) {
    asm volatile(
        "mma.sync.aligned.m16n8k16.row.col.f32.f16.f16.f32 "
        "{%0,%1,%2,%3}, {%4,%5,%6,%7}, {%8,%9}, {%0,%1,%2,%3};"
        : "+f"(c[0]), "+f"(c[1]), "+f"(c[2]), "+f"(c[3])
        : "r"(a[0]), "r"(a[1]), "r"(a[2]), "r"(a[3]), "r"(b[0]), "r"(b[1]));
}

// ---------------- type_ids dtype detection (per-warp, deterministic) ----------------
__device__ __forceinline__ int detect_is64(const int* tid32) {
    int v = tid32[2 * (threadIdx.x & 31) + 1];
    unsigned int ballot = __ballot_sync(0xFFFFFFFFu, v == 0);
    return ballot == 0xFFFFFFFFu;
}
__device__ __forceinline__ int load_type(const int* tid32, int n, int is64) {
    return is64 ? tid32[2 * n] : tid32[n];
}

// ---------------- fused routing: count + scan + scatter (one CTA) ----------------
__global__ void __launch_bounds__(1024, 1) route_kernel(const int* tid32) {
    __shared__ int cnt[K_TYPES];
    __shared__ int base[K_TYPES];
    const int tid  = threadIdx.x;
    const int lane = tid & 31;
    const int is64 = detect_is64(tid32);

    if (tid < K_TYPES) cnt[tid] = 0;
    __syncthreads();

    int k[8];
#pragma unroll
    for (int i = 0; i < 8; i++)
        k[i] = load_type(tid32, tid + i * 1024, is64);

    // warp-aggregated count
#pragma unroll
    for (int i = 0; i < 8; i++) {
        unsigned m = __match_any_sync(0xFFFFFFFFu, k[i]);
        if (lane == __ffs(m) - 1) atomicAdd(&cnt[k[i]], __popc(m));
    }
    __syncthreads();

    if (tid == 0) {
        int off = 0, nt = 0;
        for (int t = 0; t < K_TYPES; t++) {
            base[t] = off;
            int c = cnt[t];
            for (int q = 0; q < c; q += BM) {
                g_tile_type[nt] = t;
                g_tile_base[nt] = off + q;
                g_tile_rows[nt] = min(BM, c - q);
                nt++;
            }
            off += c;
        }
        g_num_tiles = nt;
    }
    __syncthreads();

    if (tid < K_TYPES) cnt[tid] = base[tid];
    __syncthreads();

    // warp-aggregated scatter (order across warps nondeterministic;
    // outputs are permutation-invariant, so result stays deterministic)
#pragma unroll
    for (int i = 0; i < 8; i++) {
        const int n = tid + i * 1024;
        unsigned m = __match_any_sync(0xFFFFFFFFu, k[i]);
        const int leader = __ffs(m) - 1;
        const int rank = __popc(m & ((1u << lane) - 1u));
        int b = 0;
        if (lane == leader) b = atomicAdd(&cnt[k[i]], __popc(m));
        b = __shfl_sync(0xFFFFFFFFu, b, leader);
        g_perm[b + rank] = n;
    }
}

// ---------------- conversions ----------------
__global__ void convert_x_kernel(const float* __restrict__ x) {
    size_t i = ((size_t)blockIdx.x * blockDim.x + threadIdx.x) * 8;
    float4 v0 = *(const float4*)(x + i);
    float4 v1 = *(const float4*)(x + i + 4);
    float v[8] = {v0.x, v0.y, v0.z, v0.w, v1.x, v1.y, v1.z, v1.w};
    __half h[8], l[8];
#pragma unroll
    for (int j = 0; j < 8; j++) {
        h[j] = __float2half_rn(v[j]);
        l[j] = __float2half_rn(v[j] - __half2float(h[j]));
    }
    *(uint4*)(g_xh + i) = *(uint4*)h;
    *(uint4*)(g_xl + i) = *(uint4*)l;
}
__global__ void convert_w_kernel(const float* __restrict__ W) {
    size_t i = ((size_t)blockIdx.x * blockDim.x + threadIdx.x) * 8;
    float4 v0 = *(const float4*)(W + i);
    float4 v1 = *(const float4*)(W + i + 4);
    float v[8] = {v0.x, v0.y, v0.z, v0.w, v1.x, v1.y, v1.z, v1.w};
    __half h[8];
#pragma unroll
    for (int j = 0; j < 8; j++) h[j] = __float2half_rn(v[j]);
    *(uint4*)(g_wh + i) = *(uint4*)h;
}

// ---------------- grouped fp16 mma.sync GEMM (tail fused) ----------------
__global__ void __launch_bounds__(256, 2) gemm_mma_kernel(
    const float* __restrict__ bias, float* __restrict__ out)
{
    const int tile = blockIdx.x;
    if (tile >= g_num_tiles) return;

    extern __shared__ __align__(16) char dynsm[];
    char* smAh = dynsm;
    char* smAl = dynsm + NSTAGE * SZA;
    char* smB  = dynsm + 2 * NSTAGE * SZA;
    __shared__ int   ridx[BM];
    __shared__ float bs[BN];

    const int tid  = threadIdx.x;
    const int lane = tid & 31;
    const int wid  = tid >> 5;
    const int warp_m = wid & 3;
    const int warp_n = wid >> 2;

    const int ktype = g_tile_type[tile];
    const int rbase = g_tile_base[tile];
    const int rows  = g_tile_rows[tile];
    const int col0  = blockIdx.y * BN;

    if (tid < BM) ridx[tid] = (tid < rows) ? g_perm[rbase + tid] : -1;
    if (tid < BN) bs[tid] = bias[(size_t)ktype * E_OUT + col0 + tid];
    __syncthreads();

    // fused one-hot tail: y==0 CTAs write cols [E_OUT, E_OUT+8) for their rows
    if (blockIdx.y == 0 && tid < BM) {
        const int row = ridx[tid];
        if (row >= 0) {
            float v[8] = {0.f, 0.f, 0.f, 0.f, 0.f, 0.f, 0.f, 0.f};
            v[ktype] = 1.0f;
            float* p = out + (size_t)row * OUT_COLS + E_OUT;
            *(float4*)(p)     = make_float4(v[0], v[1], v[2], v[3]);
            *(float4*)(p + 4) = make_float4(v[4], v[5], v[6], v[7]);
        }
    }

    // ---- per-thread cp.async descriptors ----
    const int ar = tid >> 1;
    const int arow = ridx[ar];
    const uint32_t asz = (arow >= 0) ? 16u : 0u;
    const size_t aoff = (size_t)(arow >= 0 ? arow : 0) * D_IN + (tid & 1) * 16;
    const uint32_t ahDst0 = smem_u32(smAh) + (uint32_t)(ar * A_STRIDE + (tid & 1) * 32);
    const uint32_t alDst0 = smem_u32(smAl) + (uint32_t)(ar * A_STRIDE + (tid & 1) * 32);
    const int br = tid >> 3;
    const int bc = tid & 7;
    const size_t boff = (size_t)(ktype * D_IN) * E_OUT + (size_t)br * E_OUT + col0 + bc * 8;
    const uint32_t bDst0 = smem_u32(smB) + (uint32_t)(br * B_STRIDE + bc * 16);

    auto stage_load = [&](int s) {
        const uint32_t buf = (uint32_t)(s % NSTAGE);
        const int kk = s * BK;
        const __half* ah = g_xh + aoff + kk;
        const __half* al = g_xl + aoff + kk;
        const __half* bsrc = g_wh + boff + (size_t)kk * E_OUT;
        const uint32_t ahD = ahDst0 + buf * SZA;
        const uint32_t alD = alDst0 + buf * SZA;
        const uint32_t bD  = bDst0 + buf * SZB;
        CP_ASYNC16(ahD,      ah,     asz);
        CP_ASYNC16(ahD + 16, ah + 8, asz);
        CP_ASYNC16(alD,      al,     asz);
        CP_ASYNC16(alD + 16, al + 8, asz);
        CP_ASYNC16(bD,       bsrc,      16u);
        CP_ASYNC16(bD + 128, bsrc + 64, 16u);
    };

    const uint32_t aFragOff =
        (uint32_t)((warp_m * 32 + (lane & 15)) * A_STRIDE + (lane >> 4) * 16);
    const uint32_t ahBase = smem_u32(smAh) + aFragOff;
    const uint32_t alBase = smem_u32(smAl) + aFragOff;
    const uint32_t bBase = smem_u32(smB) +
        (uint32_t)((lane & 15) * B_STRIDE + (lane >> 4) * 16 + warp_n * 128);

    float acc[2][8][4];
#pragma unroll
    for (int mi = 0; mi < 2; mi++)
#pragma unroll
        for (int ni = 0; ni < 8; ni++)
#pragma unroll
            for (int j = 0; j < 4; j++) acc[mi][ni][j] = 0.0f;

    stage_load(0); CP_COMMIT();
    stage_load(1); CP_COMMIT();

    for (int s = 0; s < NITER; s++) {
        CP_WAIT(1);
        __syncthreads();
        if (s + 2 < NITER) { stage_load(s + 2); CP_COMMIT(); }

        const uint32_t buf = (uint32_t)(s % NSTAGE);
        const uint32_t ahB = ahBase + buf * SZA;
        const uint32_t alB = alBase + buf * SZA;
        const uint32_t bB  = bBase + buf * SZB;
#pragma unroll
        for (int kst = 0; kst < 2; kst++) {
            uint32_t bfr[8][2];
#pragma unroll
            for (int nj = 0; nj < 4; nj++)
                ldmatrix_x4_trans(bfr[2 * nj][0], bfr[2 * nj][1],
                                  bfr[2 * nj + 1][0], bfr[2 * nj + 1][1],
                                  bB + kst * 16 * B_STRIDE + nj * 32);
            uint32_t afr[2][4];
#pragma unroll
            for (int mi = 0; mi < 2; mi++)
                ldmatrix_x4(afr[mi][0], afr[mi][1], afr[mi][2], afr[mi][3],
                            ahB + mi * 16 * A_STRIDE + kst * 32);
#pragma unroll
            for (int mi = 0; mi < 2; mi++)
#pragma unroll
                for (int ni = 0; ni < 8; ni++)
                    mma16816(acc[mi][ni], afr[mi], bfr[ni]);
#pragma unroll
            for (int mi = 0; mi < 2; mi++)
                ldmatrix_x4(afr[mi][0], afr[mi][1], afr[mi][2], afr[mi][3],
                            alB + mi * 16 * A_STRIDE + kst * 32);
#pragma unroll
            for (int mi = 0; mi < 2; mi++)
#pragma unroll
                for (int ni = 0; ni < 8; ni++)
                    mma16816(acc[mi][ni], afr[mi], bfr[ni]);
        }
    }

    // ---- epilogue: bias + gathered store ----
#pragma unroll
    for (int mi = 0; mi < 2; mi++) {
        const int r0 = warp_m * 32 + mi * 16 + (lane >> 2);
        const int r1 = r0 + 8;
        const int g0 = ridx[r0];
        const int g1 = ridx[r1];
#pragma unroll
        for (int ni = 0; ni < 8; ni++) {
            const int col = warp_n * 64 + ni * 8 + (lane & 3) * 2;
            const float b0 = bs[col], b1 = bs[col + 1];
            if (g0 >= 0) {
                float2 v = {acc[mi][ni][0] + b0, acc[mi][ni][1] + b1};
                *(float2*)(out + (size_t)g0 * OUT_COLS + col0 + col) = v;
            }
            if (g1 >= 0) {
                float2 v = {acc[mi][ni][2] + b0, acc[mi][ni][3] + b1};
                *(float2*)(out + (size_t)g1 * OUT_COLS + col0 + col) = v;
            }
        }
    }
}

// ---------------- launch ----------------
extern "C" void kernel_launch(void* const* d_in, const int* in_sizes, int n_in,
                              void* d_out, int out_size) {
    const float* x     = (const float*)d_in[0];
    const int*   tid32 = (const int*)d_in[1];
    const float* W     = (const float*)d_in[2];
    const float* b     = (const float*)d_in[3];
    float* out = (float*)d_out;

    cudaFuncSetAttribute(gemm_mma_kernel, cudaFuncAttributeMaxDynamicSharedMemorySize,
                         DYN_SMEM);

    route_kernel<<<1, 1024>>>(tid32);
    convert_x_kernel<<<(N_ITEMS * D_IN / 8) / 256, 256>>>(x);
    convert_w_kernel<<<(K_TYPES * D_IN * E_OUT / 8) / 256, 256>>>(W);

    dim3 grid(MAX_TILES, E_OUT / BN);
    gemm_mma_kernel<<<grid, 256, DYN_SMEM>>>(b, out);
}